// round 12
// baseline (speedup 1.0000x reference)
#include <cuda_runtime.h>
#include <math.h>

// ---------------------------------------------------------------------------
// PortfolioGAT: 2-layer GAT, N=100000 nodes, 1.6M edges + self loops.
// Layer 1: 128 -> (2 heads x 16), concat -> 32, + bias, ELU.
// Layer 2: 32 -> 1 (1 head), + bias.
// Segment softmax over incoming edges per dst via atomicMax(key)/atomicAdd.
// ---------------------------------------------------------------------------

#define MAXN 100000
#define C1 32          // layer-1 output channels (2 heads x 16)
#define NEG_SLOPE 0.2f

// ---- scratch (device globals; no allocation allowed) ----------------------
__device__ float        g_h1  [MAXN * C1];   // x @ W1
__device__ float        g_out1[MAXN * C1];   // layer-1 aggregation (init = b1)
__device__ float        g_as1 [MAXN * 2];
__device__ float        g_ad1 [MAXN * 2];
__device__ unsigned int g_m1  [MAXN * 2];    // max keys, later decoded floats
__device__ float        g_d1  [MAXN * 2];    // denom, later reciprocal
__device__ float        g_h2  [MAXN];
__device__ float        g_as2 [MAXN];
__device__ float        g_ad2 [MAXN];
__device__ unsigned int g_m2  [MAXN];
__device__ float        g_d2  [MAXN];

// ---- helpers ---------------------------------------------------------------
// Monotone float <-> uint key so atomicMax(uint) == float max (no NaNs here).
__device__ __forceinline__ unsigned int fkey(float f) {
    unsigned int b = __float_as_uint(f);
    return (b & 0x80000000u) ? ~b : (b | 0x80000000u);
}
__device__ __forceinline__ float funkey(unsigned int k) {
    unsigned int b = (k & 0x80000000u) ? (k & 0x7fffffffu) : ~k;
    return __uint_as_float(b);
}
__device__ __forceinline__ float lrelu(float v) { return v > 0.f ? v : NEG_SLOPE * v; }

__device__ __forceinline__ void red_add_v4(float* addr, float a, float b, float c, float d) {
    asm volatile("red.global.add.v4.f32 [%0], {%1,%2,%3,%4};"
                 :: "l"(addr), "f"(a), "f"(b), "f"(c), "f"(d) : "memory");
}

__device__ __forceinline__ void get_edge(const int* __restrict__ ei, int i, int E,
                                         int& s, int& d) {
    if (i < E) { s = ei[i]; d = ei[E + i]; }
    else       { s = i - E; d = s; }            // self loop appended at the end
}

// ---- init: biases into accumulators, zero max-keys / denoms ----------------
__global__ void k_init(float* __restrict__ out,
                       const float* __restrict__ b1,
                       const float* __restrict__ b2, int N) {
    int i = blockIdx.x * blockDim.x + threadIdx.x;
    if (i < N * C1) g_out1[i] = b1[i & (C1 - 1)];
    if (i < N * 2) { g_m1[i] = 0u; g_d1[i] = 0.f; }
    if (i < N)     { g_m2[i] = 0u; g_d2[i] = 0.f; out[i] = b2[0]; }
}

// ---- GEMM: h1 = x @ W1, plus per-node attention projections -----------------
// Block: 256 threads, 64 nodes. Thread = 2 nodes x 4 cols (8 accumulators).
// W1 (16KB) + x-tile (64x68 padded, 17.4KB) in smem. FFMA-bound by design.
__global__ __launch_bounds__(256)
void k_gemm(const float* __restrict__ x, const float* __restrict__ W1,
            const float* __restrict__ a_s, const float* __restrict__ a_d, int N) {
    __shared__ float sW[128 * 32];   // [k][c]
    __shared__ float sx[64 * 68];    // [node][k], stride 68 (4B-align + bank spread)

    int tid = threadIdx.x;
    for (int i = tid; i < 128 * 32; i += 256) sW[i] = W1[i];

    int base = blockIdx.x * 64;
    int col4 = (tid & 7) * 4;        // output cols col4..col4+3
    int n0   = (tid >> 3) * 2;       // local nodes n0, n0+1

    float acc[2][4] = {{0.f,0.f,0.f,0.f},{0.f,0.f,0.f,0.f}};

    for (int kc = 0; kc < 128; kc += 64) {
        __syncthreads();
        // stage x[base..base+63][kc..kc+63]: 1024 float4, 4 per thread
        #pragma unroll
        for (int it = 0; it < 4; ++it) {
            int slot = tid + it * 256;
            int row  = slot >> 4;
            int cq   = slot & 15;
            int gn   = base + row;
            float4 v = make_float4(0.f, 0.f, 0.f, 0.f);
            if (gn < N) v = *(const float4*)&x[gn * 128 + kc + cq * 4];
            *(float4*)&sx[row * 68 + cq * 4] = v;
        }
        __syncthreads();

        #pragma unroll 16
        for (int k = 0; k < 64; ++k) {
            float4 w = *(const float4*)&sW[(kc + k) * 32 + col4];
            float x0 = sx[n0 * 68 + k];
            float x1 = sx[(n0 + 1) * 68 + k];
            acc[0][0] = fmaf(x0, w.x, acc[0][0]);
            acc[0][1] = fmaf(x0, w.y, acc[0][1]);
            acc[0][2] = fmaf(x0, w.z, acc[0][2]);
            acc[0][3] = fmaf(x0, w.w, acc[0][3]);
            acc[1][0] = fmaf(x1, w.x, acc[1][0]);
            acc[1][1] = fmaf(x1, w.y, acc[1][1]);
            acc[1][2] = fmaf(x1, w.z, acc[1][2]);
            acc[1][3] = fmaf(x1, w.w, acc[1][3]);
        }
    }

    // epilogue: write h1 and reduce attention projections
    int head = col4 >> 4;
    int cc   = col4 & 15;
    float as4[4], ad4[4];
    #pragma unroll
    for (int c = 0; c < 4; ++c) {
        as4[c] = a_s[head * 16 + cc + c];
        ad4[c] = a_d[head * 16 + cc + c];
    }
    #pragma unroll
    for (int j = 0; j < 2; ++j) {
        int n = base + n0 + j;
        float va = acc[j][0]*as4[0] + acc[j][1]*as4[1] + acc[j][2]*as4[2] + acc[j][3]*as4[3];
        float vd = acc[j][0]*ad4[0] + acc[j][1]*ad4[1] + acc[j][2]*ad4[2] + acc[j][3]*ad4[3];
        // sum over the 4 lanes of this head (tn & 3): xor-1, xor-2 stay in-group
        va += __shfl_xor_sync(0xffffffffu, va, 1);
        va += __shfl_xor_sync(0xffffffffu, va, 2);
        vd += __shfl_xor_sync(0xffffffffu, vd, 1);
        vd += __shfl_xor_sync(0xffffffffu, vd, 2);
        if (n < N) {
            *(float4*)&g_h1[n * C1 + col4] =
                make_float4(acc[j][0], acc[j][1], acc[j][2], acc[j][3]);
            if ((tid & 3) == 0) {
                g_as1[n * 2 + head] = va;
                g_ad1[n * 2 + head] = vd;
            }
        }
    }
}

// ---- layer-1 edge passes ----------------------------------------------------
__global__ void k_max1(const int* __restrict__ ei, int E, int ET) {
    int i = blockIdx.x * blockDim.x + threadIdx.x;
    if (i >= ET) return;
    int s, d; get_edge(ei, i, E, s, d);
    float2 as = *(const float2*)&g_as1[s * 2];
    float2 ad = *(const float2*)&g_ad1[d * 2];
    atomicMax(&g_m1[d * 2 + 0], fkey(lrelu(as.x + ad.x)));
    atomicMax(&g_m1[d * 2 + 1], fkey(lrelu(as.y + ad.y)));
}

__global__ void k_sum1(const int* __restrict__ ei, int E, int ET) {
    int i = blockIdx.x * blockDim.x + threadIdx.x;
    if (i >= ET) return;
    int s, d; get_edge(ei, i, E, s, d);
    float2 as = *(const float2*)&g_as1[s * 2];
    float2 ad = *(const float2*)&g_ad1[d * 2];
    float e0 = lrelu(as.x + ad.x);
    float e1 = lrelu(as.y + ad.y);
    atomicAdd(&g_d1[d * 2 + 0], __expf(e0 - funkey(g_m1[d * 2 + 0])));
    atomicAdd(&g_d1[d * 2 + 1], __expf(e1 - funkey(g_m1[d * 2 + 1])));
}

__global__ void k_fin1(int N2) {   // N2 = 2*N
    int i = blockIdx.x * blockDim.x + threadIdx.x;
    if (i >= N2) return;
    g_d1[i] = 1.f / (g_d1[i] + 1e-16f);
    g_m1[i] = __float_as_uint(funkey(g_m1[i]));   // decode in place
}

// thread = (edge, head); pair covers a contiguous 128B of h1[s] / out1[d]
__global__ void k_agg1(const int* __restrict__ ei, int E, int ET) {
    int t = blockIdx.x * blockDim.x + threadIdx.x;
    int i = t >> 1;
    if (i >= ET) return;
    int head = t & 1;
    int s, d; get_edge(ei, i, E, s, d);
    float e = lrelu(g_as1[s * 2 + head] + g_ad1[d * 2 + head]);
    float w = __expf(e - __uint_as_float(g_m1[d * 2 + head])) * g_d1[d * 2 + head];
    const float4* hp = (const float4*)&g_h1[s * C1 + head * 16];
    float*        op = &g_out1[d * C1 + head * 16];
    #pragma unroll
    for (int j = 0; j < 4; ++j) {
        float4 v = hp[j];
        red_add_v4(op + j * 4, w * v.x, w * v.y, w * v.z, w * v.w);
    }
}

// ---- ELU + layer-2 projection ----------------------------------------------
__global__ void k_h2(const float* __restrict__ W2,
                     const float* __restrict__ As2,
                     const float* __restrict__ Ad2, int N) {
    int n = blockIdx.x * blockDim.x + threadIdx.x;
    if (n >= N) return;
    float acc = 0.f;
    #pragma unroll
    for (int j = 0; j < 8; ++j) {
        float4 v = *(const float4*)&g_out1[n * C1 + j * 4];
        float4 w = *(const float4*)&W2[j * 4];
        v.x = v.x > 0.f ? v.x : expm1f(v.x);
        v.y = v.y > 0.f ? v.y : expm1f(v.y);
        v.z = v.z > 0.f ? v.z : expm1f(v.z);
        v.w = v.w > 0.f ? v.w : expm1f(v.w);
        acc += v.x * w.x + v.y * w.y + v.z * w.z + v.w * w.w;
    }
    g_h2[n]  = acc;
    g_as2[n] = acc * As2[0];
    g_ad2[n] = acc * Ad2[0];
}

// ---- layer-2 edge passes ----------------------------------------------------
__global__ void k_max2(const int* __restrict__ ei, int E, int ET) {
    int i = blockIdx.x * blockDim.x + threadIdx.x;
    if (i >= ET) return;
    int s, d; get_edge(ei, i, E, s, d);
    atomicMax(&g_m2[d], fkey(lrelu(g_as2[s] + g_ad2[d])));
}

__global__ void k_sum2(const int* __restrict__ ei, int E, int ET) {
    int i = blockIdx.x * blockDim.x + threadIdx.x;
    if (i >= ET) return;
    int s, d; get_edge(ei, i, E, s, d);
    float e = lrelu(g_as2[s] + g_ad2[d]);
    atomicAdd(&g_d2[d], __expf(e - funkey(g_m2[d])));
}

__global__ void k_fin2(int N) {
    int i = blockIdx.x * blockDim.x + threadIdx.x;
    if (i >= N) return;
    g_d2[i] = 1.f / (g_d2[i] + 1e-16f);
    g_m2[i] = __float_as_uint(funkey(g_m2[i]));
}

__global__ void k_agg2(const int* __restrict__ ei, float* __restrict__ out,
                       int E, int ET) {
    int i = blockIdx.x * blockDim.x + threadIdx.x;
    if (i >= ET) return;
    int s, d; get_edge(ei, i, E, s, d);
    float e = lrelu(g_as2[s] + g_ad2[d]);
    float w = __expf(e - __uint_as_float(g_m2[d])) * g_d2[d];
    atomicAdd(&out[d], w * g_h2[s]);
}

// ---- launch ------------------------------------------------------------------
extern "C" void kernel_launch(void* const* d_in, const int* in_sizes, int n_in,
                              void* d_out, int out_size) {
    const float* x     = (const float*)d_in[0];
    const int*   ei    = (const int*)  d_in[1];
    const float* W1    = (const float*)d_in[2];
    const float* a_s1  = (const float*)d_in[3];
    const float* a_d1  = (const float*)d_in[4];
    const float* b1    = (const float*)d_in[5];
    const float* W2    = (const float*)d_in[6];
    const float* a_s2  = (const float*)d_in[7];
    const float* a_d2  = (const float*)d_in[8];
    const float* b2    = (const float*)d_in[9];
    float*       out   = (float*)d_out;

    int N  = in_sizes[0] / 128;
    int E  = in_sizes[1] / 2;
    int ET = E + N;
    if (N > MAXN) return;

    const int T = 256;
    auto blks = [T](long long n) { return (int)((n + T - 1) / T); };

    k_init<<<blks((long long)N * C1), T>>>(out, b1, b2, N);
    k_gemm<<<(N + 63) / 64, T>>>(x, W1, a_s1, a_d1, N);
    k_max1<<<blks(ET), T>>>(ei, E, ET);
    k_sum1<<<blks(ET), T>>>(ei, E, ET);
    k_fin1<<<blks(2 * N), T>>>(2 * N);
    k_agg1<<<blks(2LL * ET), T>>>(ei, E, ET);
    k_h2  <<<blks(N), T>>>(W2, a_s2, a_d2, N);
    k_max2<<<blks(ET), T>>>(ei, E, ET);
    k_sum2<<<blks(ET), T>>>(ei, E, ET);
    k_fin2<<<blks(N), T>>>(N);
    k_agg2<<<blks(ET), T>>>(ei, out, E, ET);
}

// round 13
// speedup vs baseline: 1.7140x; 1.7140x over previous
#include <cuda_runtime.h>
#include <math.h>

// ---------------------------------------------------------------------------
// PortfolioGAT: 2-layer GAT, N=100000 nodes, 1.6M edges + self loops.
// Round 12: drop max pass (scores are O(1), exp never overflows); fuse
// softmax-denominator and aggregation into ONE edge pass per layer using
// unnormalized accumulation + deferred per-node division.
// ---------------------------------------------------------------------------

#define MAXN 100000
#define C1 32          // layer-1 output channels (2 heads x 16)
#define NEG_SLOPE 0.2f

// ---- scratch (device globals; no allocation allowed) ----------------------
__device__ float g_h1  [MAXN * C1];   // x @ W1
__device__ float g_out1[MAXN * C1];   // layer-1 unnormalized numerator
__device__ float g_as1 [MAXN * 2];
__device__ float g_ad1 [MAXN * 2];
__device__ float g_d1  [MAXN * 2];    // layer-1 denominators
__device__ float g_h2  [MAXN];
__device__ float g_as2 [MAXN];
__device__ float g_ad2 [MAXN];
__device__ float g_nd2 [MAXN * 2];    // layer-2 {numerator, denominator} pairs

// ---- helpers ---------------------------------------------------------------
__device__ __forceinline__ float lrelu(float v) { return v > 0.f ? v : NEG_SLOPE * v; }

__device__ __forceinline__ void red_add_v4(float* addr, float a, float b, float c, float d) {
    asm volatile("red.global.add.v4.f32 [%0], {%1,%2,%3,%4};"
                 :: "l"(addr), "f"(a), "f"(b), "f"(c), "f"(d) : "memory");
}
__device__ __forceinline__ void red_add_v2(float* addr, float a, float b) {
    asm volatile("red.global.add.v2.f32 [%0], {%1,%2};"
                 :: "l"(addr), "f"(a), "f"(b) : "memory");
}

__device__ __forceinline__ void get_edge(const int* __restrict__ ei, int i, int E,
                                         int& s, int& d) {
    if (i < E) { s = ei[i]; d = ei[E + i]; }
    else       { s = i - E; d = s; }            // self loop appended at the end
}

// ---- init: zero all accumulators -------------------------------------------
__global__ void k_init(int N) {
    int i = blockIdx.x * blockDim.x + threadIdx.x;
    if (i < N * C1) g_out1[i] = 0.f;
    if (i < N * 2) { g_d1[i] = 0.f; g_nd2[i] = 0.f; }
}

// ---- GEMM: h1 = x @ W1, plus per-node attention projections -----------------
// Block: 256 threads, 64 nodes. Thread = 2 nodes x 4 cols (8 accumulators).
__global__ __launch_bounds__(256)
void k_gemm(const float* __restrict__ x, const float* __restrict__ W1,
            const float* __restrict__ a_s, const float* __restrict__ a_d, int N) {
    __shared__ float sW[128 * 32];   // [k][c]
    __shared__ float sx[64 * 68];    // [node][k], stride 68

    int tid = threadIdx.x;
    for (int i = tid; i < 128 * 32; i += 256) sW[i] = W1[i];

    int base = blockIdx.x * 64;
    int col4 = (tid & 7) * 4;        // output cols col4..col4+3
    int n0   = (tid >> 3) * 2;       // local nodes n0, n0+1

    float acc[2][4] = {{0.f,0.f,0.f,0.f},{0.f,0.f,0.f,0.f}};

    for (int kc = 0; kc < 128; kc += 64) {
        __syncthreads();
        #pragma unroll
        for (int it = 0; it < 4; ++it) {
            int slot = tid + it * 256;
            int row  = slot >> 4;
            int cq   = slot & 15;
            int gn   = base + row;
            float4 v = make_float4(0.f, 0.f, 0.f, 0.f);
            if (gn < N) v = *(const float4*)&x[gn * 128 + kc + cq * 4];
            *(float4*)&sx[row * 68 + cq * 4] = v;
        }
        __syncthreads();

        #pragma unroll 16
        for (int k = 0; k < 64; ++k) {
            float4 w = *(const float4*)&sW[(kc + k) * 32 + col4];
            float x0 = sx[n0 * 68 + k];
            float x1 = sx[(n0 + 1) * 68 + k];
            acc[0][0] = fmaf(x0, w.x, acc[0][0]);
            acc[0][1] = fmaf(x0, w.y, acc[0][1]);
            acc[0][2] = fmaf(x0, w.z, acc[0][2]);
            acc[0][3] = fmaf(x0, w.w, acc[0][3]);
            acc[1][0] = fmaf(x1, w.x, acc[1][0]);
            acc[1][1] = fmaf(x1, w.y, acc[1][1]);
            acc[1][2] = fmaf(x1, w.z, acc[1][2]);
            acc[1][3] = fmaf(x1, w.w, acc[1][3]);
        }
    }

    int head = col4 >> 4;
    int cc   = col4 & 15;
    float as4[4], ad4[4];
    #pragma unroll
    for (int c = 0; c < 4; ++c) {
        as4[c] = a_s[head * 16 + cc + c];
        ad4[c] = a_d[head * 16 + cc + c];
    }
    #pragma unroll
    for (int j = 0; j < 2; ++j) {
        int n = base + n0 + j;
        float va = acc[j][0]*as4[0] + acc[j][1]*as4[1] + acc[j][2]*as4[2] + acc[j][3]*as4[3];
        float vd = acc[j][0]*ad4[0] + acc[j][1]*ad4[1] + acc[j][2]*ad4[2] + acc[j][3]*ad4[3];
        va += __shfl_xor_sync(0xffffffffu, va, 1);
        va += __shfl_xor_sync(0xffffffffu, va, 2);
        vd += __shfl_xor_sync(0xffffffffu, vd, 1);
        vd += __shfl_xor_sync(0xffffffffu, vd, 2);
        if (n < N) {
            *(float4*)&g_h1[n * C1 + col4] =
                make_float4(acc[j][0], acc[j][1], acc[j][2], acc[j][3]);
            if ((tid & 3) == 0) {
                g_as1[n * 2 + head] = va;
                g_ad1[n * 2 + head] = vd;
            }
        }
    }
}

// ---- layer-1 fused edge pass: unnormalized softmax-weighted scatter ---------
// thread = (edge, head); pair covers contiguous 128B of h1[s] / out1[d].
__global__ void k_edge1(const int* __restrict__ ei, int E, int ET) {
    int t = blockIdx.x * blockDim.x + threadIdx.x;
    int i = t >> 1;
    if (i >= ET) return;
    int head = t & 1;
    int s, d; get_edge(ei, i, E, s, d);
    float w = __expf(lrelu(g_as1[s * 2 + head] + g_ad1[d * 2 + head]));
    atomicAdd(&g_d1[d * 2 + head], w);
    const float4* hp = (const float4*)&g_h1[s * C1 + head * 16];
    float*        op = &g_out1[d * C1 + head * 16];
    #pragma unroll
    for (int j = 0; j < 4; ++j) {
        float4 v = hp[j];
        red_add_v4(op + j * 4, w * v.x, w * v.y, w * v.z, w * v.w);
    }
}

// ---- normalize + bias + ELU + layer-2 projection ----------------------------
__global__ void k_h2(const float* __restrict__ b1,
                     const float* __restrict__ W2,
                     const float* __restrict__ As2,
                     const float* __restrict__ Ad2, int N) {
    int n = blockIdx.x * blockDim.x + threadIdx.x;
    if (n >= N) return;
    float r0 = 1.f / (g_d1[n * 2 + 0] + 1e-16f);
    float r1 = 1.f / (g_d1[n * 2 + 1] + 1e-16f);
    float acc = 0.f;
    #pragma unroll
    for (int j = 0; j < 8; ++j) {
        float r = (j < 4) ? r0 : r1;
        float4 v = *(const float4*)&g_out1[n * C1 + j * 4];
        float4 bb = *(const float4*)&b1[j * 4];
        float4 w = *(const float4*)&W2[j * 4];
        v.x = v.x * r + bb.x;
        v.y = v.y * r + bb.y;
        v.z = v.z * r + bb.z;
        v.w = v.w * r + bb.w;
        v.x = v.x > 0.f ? v.x : expm1f(v.x);
        v.y = v.y > 0.f ? v.y : expm1f(v.y);
        v.z = v.z > 0.f ? v.z : expm1f(v.z);
        v.w = v.w > 0.f ? v.w : expm1f(v.w);
        acc += v.x * w.x + v.y * w.y + v.z * w.z + v.w * w.w;
    }
    g_h2[n]  = acc;
    g_as2[n] = acc * As2[0];
    g_ad2[n] = acc * Ad2[0];
}

// ---- layer-2 fused edge pass -------------------------------------------------
__global__ void k_edge2(const int* __restrict__ ei, int E, int ET) {
    int i = blockIdx.x * blockDim.x + threadIdx.x;
    if (i >= ET) return;
    int s, d; get_edge(ei, i, E, s, d);
    float w = __expf(lrelu(g_as2[s] + g_ad2[d]));
    red_add_v2(&g_nd2[d * 2], w * g_h2[s], w);   // {numerator, denominator}
}

// ---- finalize -----------------------------------------------------------------
__global__ void k_fin(float* __restrict__ out, const float* __restrict__ b2, int N) {
    int n = blockIdx.x * blockDim.x + threadIdx.x;
    if (n >= N) return;
    float2 nd = *(const float2*)&g_nd2[n * 2];
    out[n] = nd.x / (nd.y + 1e-16f) + b2[0];
}

// ---- launch ------------------------------------------------------------------
extern "C" void kernel_launch(void* const* d_in, const int* in_sizes, int n_in,
                              void* d_out, int out_size) {
    const float* x     = (const float*)d_in[0];
    const int*   ei    = (const int*)  d_in[1];
    const float* W1    = (const float*)d_in[2];
    const float* a_s1  = (const float*)d_in[3];
    const float* a_d1  = (const float*)d_in[4];
    const float* b1    = (const float*)d_in[5];
    const float* W2    = (const float*)d_in[6];
    const float* a_s2  = (const float*)d_in[7];
    const float* a_d2  = (const float*)d_in[8];
    const float* b2    = (const float*)d_in[9];
    float*       out   = (float*)d_out;

    int N  = in_sizes[0] / 128;
    int E  = in_sizes[1] / 2;
    int ET = E + N;
    if (N > MAXN) return;

    const int T = 256;
    auto blks = [T](long long n) { return (int)((n + T - 1) / T); };

    k_init <<<blks((long long)N * C1), T>>>(N);
    k_gemm <<<(N + 63) / 64, T>>>(x, W1, a_s1, a_d1, N);
    k_edge1<<<blks(2LL * ET), T>>>(ei, E, ET);
    k_h2   <<<blks(N), T>>>(b1, W2, a_s2, a_d2, N);
    k_edge2<<<blks(ET), T>>>(ei, E, ET);
    k_fin  <<<blks(N), T>>>(out, b2, N);
}

// round 14
// speedup vs baseline: 1.8804x; 1.0971x over previous
#include <cuda_runtime.h>
#include <math.h>

// ---------------------------------------------------------------------------
// PortfolioGAT: 2-layer GAT, N=100000, 1.6M edges + self loops.
// Round 13: build CSR (by dst) per call; warp-per-node gather aggregation
// (no atomic scatter of the 32-wide payload); fuse normalize+bias+ELU+W2
// projection into the layer-1 aggregation kernel; layer 2 gather + reduce.
// ---------------------------------------------------------------------------

#define MAXN 100000
#define MAXE 1600000
#define C1 32
#define NEG_SLOPE 0.2f

// ---- scratch ----------------------------------------------------------------
__device__ int    g_cnt[MAXN];        // histogram, then scatter cursor
__device__ int    g_row[MAXN + 1];    // CSR row offsets
__device__ int    g_part[512];        // scan partials
__device__ int    g_srt[MAXE];        // src ids sorted by dst
__device__ float  g_h1 [MAXN * C1];   // x @ W1
__device__ float  g_as1[MAXN * 2];
__device__ float  g_ad1[MAXN * 2];
__device__ float2 g_sh2[MAXN];        // {as2, h2} packed
__device__ float  g_ad2[MAXN];

__device__ __forceinline__ float lrelu(float v) { return v > 0.f ? v : NEG_SLOPE * v; }

// ---- CSR build ---------------------------------------------------------------
__global__ void k_zero(int N) {
    int i = blockIdx.x * blockDim.x + threadIdx.x;
    if (i < N) g_cnt[i] = 0;
}

__global__ void k_hist(const int* __restrict__ ei, int E) {
    int i = blockIdx.x * blockDim.x + threadIdx.x;
    if (i < E) atomicAdd(&g_cnt[ei[E + i]], 1);
}

// block-level scan helper (256 threads): returns inclusive scan of v
__device__ __forceinline__ int block_incl_scan(int v, int* sWarp) {
    int lane = threadIdx.x & 31, wid = threadIdx.x >> 5;
    int x = v;
    #pragma unroll
    for (int off = 1; off < 32; off <<= 1) {
        int y = __shfl_up_sync(0xffffffffu, x, off);
        if (lane >= off) x += y;
    }
    if (lane == 31) sWarp[wid] = x;
    __syncthreads();
    if (wid == 0) {
        int t = (lane < (blockDim.x >> 5)) ? sWarp[lane] : 0;
        #pragma unroll
        for (int off = 1; off < 32; off <<= 1) {
            int y = __shfl_up_sync(0xffffffffu, t, off);
            if (lane >= off) t += y;
        }
        sWarp[lane] = t;
    }
    __syncthreads();
    if (wid > 0) x += sWarp[wid - 1];
    return x;
}

__global__ void k_scanA(int N) {   // per-block exclusive scan + block totals
    __shared__ int sWarp[32];
    int i = blockIdx.x * blockDim.x + threadIdx.x;
    int v = (i < N) ? g_cnt[i] : 0;
    int incl = block_incl_scan(v, sWarp);
    if (i <= N) g_row[i] = incl - v;          // local exclusive
    if (threadIdx.x == blockDim.x - 1) g_part[blockIdx.x] = incl;
}

__global__ void k_scanB(int nb) {  // single block of 512: exclusive scan of partials
    __shared__ int sWarp[32];
    int t = threadIdx.x;
    int v = (t < nb) ? g_part[t] : 0;
    int lane = t & 31, wid = t >> 5;
    int x = v;
    #pragma unroll
    for (int off = 1; off < 32; off <<= 1) {
        int y = __shfl_up_sync(0xffffffffu, x, off);
        if (lane >= off) x += y;
    }
    if (lane == 31) sWarp[wid] = x;
    __syncthreads();
    if (wid == 0) {
        int w = (lane < 16) ? sWarp[lane] : 0;
        #pragma unroll
        for (int off = 1; off < 32; off <<= 1) {
            int y = __shfl_up_sync(0xffffffffu, w, off);
            if (lane >= off) w += y;
        }
        sWarp[lane] = w;
    }
    __syncthreads();
    if (wid > 0) x += sWarp[wid - 1];
    if (t < nb) g_part[t] = x - v;            // exclusive
}

__global__ void k_scanC(int N, int E) {
    int i = blockIdx.x * blockDim.x + threadIdx.x;
    if (i < N) {
        int r = g_row[i] + g_part[i >> 8];
        g_row[i] = r;
        g_cnt[i] = r;                          // cursor copy
    }
    if (i == N) g_row[N] = E;
}

__global__ void k_scatter(const int* __restrict__ ei, int E) {
    int i = blockIdx.x * blockDim.x + threadIdx.x;
    if (i >= E) return;
    int s = ei[i], d = ei[E + i];
    int pos = atomicAdd(&g_cnt[d], 1);
    g_srt[pos] = s;
}

// ---- GEMM: h1 = x @ W1, plus per-node attention projections -------------------
__global__ __launch_bounds__(256)
void k_gemm(const float* __restrict__ x, const float* __restrict__ W1,
            const float* __restrict__ a_s, const float* __restrict__ a_d, int N) {
    __shared__ float sW[128 * 32];
    __shared__ float sx[64 * 68];

    int tid = threadIdx.x;
    for (int i = tid; i < 128 * 32; i += 256) sW[i] = W1[i];

    int base = blockIdx.x * 64;
    int col4 = (tid & 7) * 4;
    int n0   = (tid >> 3) * 2;

    float acc[2][4] = {{0.f,0.f,0.f,0.f},{0.f,0.f,0.f,0.f}};

    for (int kc = 0; kc < 128; kc += 64) {
        __syncthreads();
        #pragma unroll
        for (int it = 0; it < 4; ++it) {
            int slot = tid + it * 256;
            int row  = slot >> 4;
            int cq   = slot & 15;
            int gn   = base + row;
            float4 v = make_float4(0.f, 0.f, 0.f, 0.f);
            if (gn < N) v = *(const float4*)&x[gn * 128 + kc + cq * 4];
            *(float4*)&sx[row * 68 + cq * 4] = v;
        }
        __syncthreads();

        #pragma unroll 16
        for (int k = 0; k < 64; ++k) {
            float4 w = *(const float4*)&sW[(kc + k) * 32 + col4];
            float x0 = sx[n0 * 68 + k];
            float x1 = sx[(n0 + 1) * 68 + k];
            acc[0][0] = fmaf(x0, w.x, acc[0][0]);
            acc[0][1] = fmaf(x0, w.y, acc[0][1]);
            acc[0][2] = fmaf(x0, w.z, acc[0][2]);
            acc[0][3] = fmaf(x0, w.w, acc[0][3]);
            acc[1][0] = fmaf(x1, w.x, acc[1][0]);
            acc[1][1] = fmaf(x1, w.y, acc[1][1]);
            acc[1][2] = fmaf(x1, w.z, acc[1][2]);
            acc[1][3] = fmaf(x1, w.w, acc[1][3]);
        }
    }

    int head = col4 >> 4;
    int cc   = col4 & 15;
    float as4[4], ad4[4];
    #pragma unroll
    for (int c = 0; c < 4; ++c) {
        as4[c] = a_s[head * 16 + cc + c];
        ad4[c] = a_d[head * 16 + cc + c];
    }
    #pragma unroll
    for (int j = 0; j < 2; ++j) {
        int n = base + n0 + j;
        float va = acc[j][0]*as4[0] + acc[j][1]*as4[1] + acc[j][2]*as4[2] + acc[j][3]*as4[3];
        float vd = acc[j][0]*ad4[0] + acc[j][1]*ad4[1] + acc[j][2]*ad4[2] + acc[j][3]*ad4[3];
        va += __shfl_xor_sync(0xffffffffu, va, 1);
        va += __shfl_xor_sync(0xffffffffu, va, 2);
        vd += __shfl_xor_sync(0xffffffffu, vd, 1);
        vd += __shfl_xor_sync(0xffffffffu, vd, 2);
        if (n < N) {
            *(float4*)&g_h1[n * C1 + col4] =
                make_float4(acc[j][0], acc[j][1], acc[j][2], acc[j][3]);
            if ((tid & 3) == 0) {
                g_as1[n * 2 + head] = va;
                g_ad1[n * 2 + head] = vd;
            }
        }
    }
}

// ---- layer-1 aggregate + normalize + ELU + layer-2 projection, fused ---------
// One warp per dst node. lane = output channel (0-15 head0, 16-31 head1).
__global__ __launch_bounds__(256)
void k_agg1(const float* __restrict__ b1, const float* __restrict__ W2,
            const float* __restrict__ As2, const float* __restrict__ Ad2, int N) {
    int warp = (blockIdx.x * blockDim.x + threadIdx.x) >> 5;
    int lane = threadIdx.x & 31;
    if (warp >= N) return;
    int d = warp;
    bool h0 = lane < 16;

    float2 adp = *(const float2*)&g_ad1[2 * d];
    float2 asp = *(const float2*)&g_as1[2 * d];
    float ad_h = h0 ? adp.x : adp.y;

    // self loop
    float w = __expf(lrelu((h0 ? asp.x : asp.y) + ad_h));
    float den = w;
    float acc = w * g_h1[d * C1 + lane];

    int start = g_row[d], end = g_row[d + 1];
    for (int base = start; base < end; base += 32) {
        int m = end - base; if (m > 32) m = 32;
        int sb = 0;
        if (base + lane < end) sb = g_srt[base + lane];
        int k = 0;
        for (; k + 4 <= m; k += 4) {
            int s0 = __shfl_sync(0xffffffffu, sb, k);
            int s1 = __shfl_sync(0xffffffffu, sb, k + 1);
            int s2 = __shfl_sync(0xffffffffu, sb, k + 2);
            int s3 = __shfl_sync(0xffffffffu, sb, k + 3);
            float2 a0 = ((const float2*)g_as1)[s0];
            float2 a1 = ((const float2*)g_as1)[s1];
            float2 a2 = ((const float2*)g_as1)[s2];
            float2 a3 = ((const float2*)g_as1)[s3];
            float f0 = g_h1[s0 * C1 + lane];
            float f1 = g_h1[s1 * C1 + lane];
            float f2 = g_h1[s2 * C1 + lane];
            float f3 = g_h1[s3 * C1 + lane];
            float w0 = __expf(lrelu((h0 ? a0.x : a0.y) + ad_h));
            float w1 = __expf(lrelu((h0 ? a1.x : a1.y) + ad_h));
            float w2 = __expf(lrelu((h0 ? a2.x : a2.y) + ad_h));
            float w3 = __expf(lrelu((h0 ? a3.x : a3.y) + ad_h));
            acc = fmaf(w0, f0, acc); den += w0;
            acc = fmaf(w1, f1, acc); den += w1;
            acc = fmaf(w2, f2, acc); den += w2;
            acc = fmaf(w3, f3, acc); den += w3;
        }
        for (; k < m; ++k) {
            int s = __shfl_sync(0xffffffffu, sb, k);
            float2 a = ((const float2*)g_as1)[s];
            float f = g_h1[s * C1 + lane];
            float ww = __expf(lrelu((h0 ? a.x : a.y) + ad_h));
            acc = fmaf(ww, f, acc); den += ww;
        }
    }

    // normalize + bias + ELU + layer-2 projection (dot with W2 over 32 channels)
    float o = acc / den + b1[lane];
    o = o > 0.f ? o : (__expf(o) - 1.f);
    float c = o * W2[lane];
    #pragma unroll
    for (int off = 16; off; off >>= 1)
        c += __shfl_xor_sync(0xffffffffu, c, off);
    if (lane == 0) {
        g_sh2[d] = make_float2(c * As2[0], c);   // {as2, h2}
        g_ad2[d] = c * Ad2[0];
    }
}

// ---- layer-2: warp per node, lanes stride edges -------------------------------
__global__ __launch_bounds__(256)
void k_agg2(float* __restrict__ out, const float* __restrict__ b2, int N) {
    int warp = (blockIdx.x * blockDim.x + threadIdx.x) >> 5;
    int lane = threadIdx.x & 31;
    if (warp >= N) return;
    int d = warp;
    float ad = g_ad2[d];
    float num = 0.f, den = 0.f;
    int start = g_row[d], end = g_row[d + 1];
    for (int k = start + lane; k < end; k += 32) {
        int s = g_srt[k];
        float2 p = g_sh2[s];                       // {as2, h2}
        float w = __expf(lrelu(p.x + ad));
        num = fmaf(w, p.y, num); den += w;
    }
    if (lane == 0) {                               // self loop
        float2 p = g_sh2[d];
        float w = __expf(lrelu(p.x + ad));
        num = fmaf(w, p.y, num); den += w;
    }
    #pragma unroll
    for (int off = 16; off; off >>= 1) {
        num += __shfl_xor_sync(0xffffffffu, num, off);
        den += __shfl_xor_sync(0xffffffffu, den, off);
    }
    if (lane == 0) out[d] = num / den + b2[0];
}

// ---- launch --------------------------------------------------------------------
extern "C" void kernel_launch(void* const* d_in, const int* in_sizes, int n_in,
                              void* d_out, int out_size) {
    const float* x     = (const float*)d_in[0];
    const int*   ei    = (const int*)  d_in[1];
    const float* W1    = (const float*)d_in[2];
    const float* a_s1  = (const float*)d_in[3];
    const float* a_d1  = (const float*)d_in[4];
    const float* b1    = (const float*)d_in[5];
    const float* W2    = (const float*)d_in[6];
    const float* a_s2  = (const float*)d_in[7];
    const float* a_d2  = (const float*)d_in[8];
    const float* b2    = (const float*)d_in[9];
    float*       out   = (float*)d_out;

    int N  = in_sizes[0] / 128;
    int E  = in_sizes[1] / 2;
    if (N > MAXN || E > MAXE) return;

    const int T = 256;
    auto blks = [T](long long n) { return (int)((n + T - 1) / T); };
    int nb = blks(N);

    k_gemm   <<<(N + 63) / 64, T>>>(x, W1, a_s1, a_d1, N);
    k_zero   <<<nb, T>>>(N);
    k_hist   <<<blks(E), T>>>(ei, E);
    k_scanA  <<<nb, T>>>(N);
    k_scanB  <<<1, 512>>>(nb);
    k_scanC  <<<blks(N + 1), T>>>(N, E);
    k_scatter<<<blks(E), T>>>(ei, E);
    k_agg1   <<<blks((long long)N * 32), T>>>(b1, W2, a_s2, a_d2, N);
    k_agg2   <<<blks((long long)N * 32), T>>>(out, b2, N);
}

// round 15
// speedup vs baseline: 1.9427x; 1.0331x over previous
#include <cuda_runtime.h>
#include <cuda_fp16.h>
#include <math.h>

// ---------------------------------------------------------------------------
// PortfolioGAT: 2-layer GAT, N=100000, 1.6M edges + self loops.
// Round 14: h1 stored fp16 (halves dominant gather traffic); CSR build chain
// overlapped with GEMM via stream fork-join inside graph capture.
// ---------------------------------------------------------------------------

#define MAXN 100000
#define MAXE 1600000
#define C1 32
#define NEG_SLOPE 0.2f

// ---- scratch ----------------------------------------------------------------
__device__ int    g_cnt[MAXN];        // histogram, then scatter cursor
__device__ int    g_row[MAXN + 1];    // CSR row offsets
__device__ int    g_part[512];        // scan partials
__device__ int    g_srt[MAXE];        // src ids sorted by dst
__device__ __half g_h1h[MAXN * C1];   // x @ W1, fp16
__device__ float  g_as1[MAXN * 2];
__device__ float  g_ad1[MAXN * 2];
__device__ float2 g_sh2[MAXN];        // {as2, h2} packed
__device__ float  g_ad2[MAXN];

__device__ __forceinline__ float lrelu(float v) { return v > 0.f ? v : NEG_SLOPE * v; }

// ---- CSR build ---------------------------------------------------------------
__global__ void k_zero(int N) {
    int i = blockIdx.x * blockDim.x + threadIdx.x;
    if (i < N) g_cnt[i] = 0;
}

__global__ void k_hist(const int* __restrict__ ei, int E) {
    int i = blockIdx.x * blockDim.x + threadIdx.x;
    if (i < E) atomicAdd(&g_cnt[ei[E + i]], 1);
}

__device__ __forceinline__ int block_incl_scan(int v, int* sWarp) {
    int lane = threadIdx.x & 31, wid = threadIdx.x >> 5;
    int x = v;
    #pragma unroll
    for (int off = 1; off < 32; off <<= 1) {
        int y = __shfl_up_sync(0xffffffffu, x, off);
        if (lane >= off) x += y;
    }
    if (lane == 31) sWarp[wid] = x;
    __syncthreads();
    if (wid == 0) {
        int t = (lane < (blockDim.x >> 5)) ? sWarp[lane] : 0;
        #pragma unroll
        for (int off = 1; off < 32; off <<= 1) {
            int y = __shfl_up_sync(0xffffffffu, t, off);
            if (lane >= off) t += y;
        }
        sWarp[lane] = t;
    }
    __syncthreads();
    if (wid > 0) x += sWarp[wid - 1];
    return x;
}

__global__ void k_scanA(int N) {
    __shared__ int sWarp[32];
    int i = blockIdx.x * blockDim.x + threadIdx.x;
    int v = (i < N) ? g_cnt[i] : 0;
    int incl = block_incl_scan(v, sWarp);
    if (i <= N) g_row[i] = incl - v;
    if (threadIdx.x == blockDim.x - 1) g_part[blockIdx.x] = incl;
}

__global__ void k_scanB(int nb) {
    __shared__ int sWarp[32];
    int t = threadIdx.x;
    int v = (t < nb) ? g_part[t] : 0;
    int lane = t & 31, wid = t >> 5;
    int x = v;
    #pragma unroll
    for (int off = 1; off < 32; off <<= 1) {
        int y = __shfl_up_sync(0xffffffffu, x, off);
        if (lane >= off) x += y;
    }
    if (lane == 31) sWarp[wid] = x;
    __syncthreads();
    if (wid == 0) {
        int w = (lane < 16) ? sWarp[lane] : 0;
        #pragma unroll
        for (int off = 1; off < 32; off <<= 1) {
            int y = __shfl_up_sync(0xffffffffu, w, off);
            if (lane >= off) w += y;
        }
        sWarp[lane] = w;
    }
    __syncthreads();
    if (wid > 0) x += sWarp[wid - 1];
    if (t < nb) g_part[t] = x - v;
}

__global__ void k_scanC(int N, int E) {
    int i = blockIdx.x * blockDim.x + threadIdx.x;
    if (i < N) {
        int r = g_row[i] + g_part[i >> 8];
        g_row[i] = r;
        g_cnt[i] = r;
    }
    if (i == N) g_row[N] = E;
}

__global__ void k_scatter(const int* __restrict__ ei, int E) {
    int i = blockIdx.x * blockDim.x + threadIdx.x;
    if (i >= E) return;
    int s = ei[i], d = ei[E + i];
    int pos = atomicAdd(&g_cnt[d], 1);
    g_srt[pos] = s;
}

// ---- GEMM: h1 = x @ W1 (fp16 out), plus per-node attention projections --------
__global__ __launch_bounds__(256)
void k_gemm(const float* __restrict__ x, const float* __restrict__ W1,
            const float* __restrict__ a_s, const float* __restrict__ a_d, int N) {
    __shared__ float sW[128 * 32];
    __shared__ float sx[64 * 68];

    int tid = threadIdx.x;
    for (int i = tid; i < 128 * 32; i += 256) sW[i] = W1[i];

    int base = blockIdx.x * 64;
    int col4 = (tid & 7) * 4;
    int n0   = (tid >> 3) * 2;

    float acc[2][4] = {{0.f,0.f,0.f,0.f},{0.f,0.f,0.f,0.f}};

    for (int kc = 0; kc < 128; kc += 64) {
        __syncthreads();
        #pragma unroll
        for (int it = 0; it < 4; ++it) {
            int slot = tid + it * 256;
            int row  = slot >> 4;
            int cq   = slot & 15;
            int gn   = base + row;
            float4 v = make_float4(0.f, 0.f, 0.f, 0.f);
            if (gn < N) v = *(const float4*)&x[gn * 128 + kc + cq * 4];
            *(float4*)&sx[row * 68 + cq * 4] = v;
        }
        __syncthreads();

        #pragma unroll 16
        for (int k = 0; k < 64; ++k) {
            float4 w = *(const float4*)&sW[(kc + k) * 32 + col4];
            float x0 = sx[n0 * 68 + k];
            float x1 = sx[(n0 + 1) * 68 + k];
            acc[0][0] = fmaf(x0, w.x, acc[0][0]);
            acc[0][1] = fmaf(x0, w.y, acc[0][1]);
            acc[0][2] = fmaf(x0, w.z, acc[0][2]);
            acc[0][3] = fmaf(x0, w.w, acc[0][3]);
            acc[1][0] = fmaf(x1, w.x, acc[1][0]);
            acc[1][1] = fmaf(x1, w.y, acc[1][1]);
            acc[1][2] = fmaf(x1, w.z, acc[1][2]);
            acc[1][3] = fmaf(x1, w.w, acc[1][3]);
        }
    }

    int head = col4 >> 4;
    int cc   = col4 & 15;
    float as4[4], ad4[4];
    #pragma unroll
    for (int c = 0; c < 4; ++c) {
        as4[c] = a_s[head * 16 + cc + c];
        ad4[c] = a_d[head * 16 + cc + c];
    }
    #pragma unroll
    for (int j = 0; j < 2; ++j) {
        int n = base + n0 + j;
        float va = acc[j][0]*as4[0] + acc[j][1]*as4[1] + acc[j][2]*as4[2] + acc[j][3]*as4[3];
        float vd = acc[j][0]*ad4[0] + acc[j][1]*ad4[1] + acc[j][2]*ad4[2] + acc[j][3]*ad4[3];
        va += __shfl_xor_sync(0xffffffffu, va, 1);
        va += __shfl_xor_sync(0xffffffffu, va, 2);
        vd += __shfl_xor_sync(0xffffffffu, vd, 1);
        vd += __shfl_xor_sync(0xffffffffu, vd, 2);
        if (n < N) {
            __half2 p0 = __floats2half2_rn(acc[j][0], acc[j][1]);
            __half2 p1 = __floats2half2_rn(acc[j][2], acc[j][3]);
            __half2* hp = (__half2*)&g_h1h[n * C1 + col4];
            hp[0] = p0; hp[1] = p1;
            if ((tid & 3) == 0) {
                g_as1[n * 2 + head] = va;
                g_ad1[n * 2 + head] = vd;
            }
        }
    }
}

// ---- layer-1 aggregate + normalize + ELU + layer-2 projection, fused ---------
__global__ __launch_bounds__(256)
void k_agg1(const float* __restrict__ b1, const float* __restrict__ W2,
            const float* __restrict__ As2, const float* __restrict__ Ad2, int N) {
    int warp = (blockIdx.x * blockDim.x + threadIdx.x) >> 5;
    int lane = threadIdx.x & 31;
    if (warp >= N) return;
    int d = warp;
    bool h0 = lane < 16;

    float2 adp = *(const float2*)&g_ad1[2 * d];
    float2 asp = *(const float2*)&g_as1[2 * d];
    float ad_h = h0 ? adp.x : adp.y;

    // self loop
    float w = __expf(lrelu((h0 ? asp.x : asp.y) + ad_h));
    float den = w;
    float acc = w * __half2float(g_h1h[d * C1 + lane]);

    int start = g_row[d], end = g_row[d + 1];
    for (int base = start; base < end; base += 32) {
        int m = end - base; if (m > 32) m = 32;
        int sb = 0;
        if (base + lane < end) sb = g_srt[base + lane];
        int k = 0;
        for (; k + 4 <= m; k += 4) {
            int s0 = __shfl_sync(0xffffffffu, sb, k);
            int s1 = __shfl_sync(0xffffffffu, sb, k + 1);
            int s2 = __shfl_sync(0xffffffffu, sb, k + 2);
            int s3 = __shfl_sync(0xffffffffu, sb, k + 3);
            float2 a0 = __ldg(&((const float2*)g_as1)[s0]);
            float2 a1 = __ldg(&((const float2*)g_as1)[s1]);
            float2 a2 = __ldg(&((const float2*)g_as1)[s2]);
            float2 a3 = __ldg(&((const float2*)g_as1)[s3]);
            float f0 = __half2float(g_h1h[s0 * C1 + lane]);
            float f1 = __half2float(g_h1h[s1 * C1 + lane]);
            float f2 = __half2float(g_h1h[s2 * C1 + lane]);
            float f3 = __half2float(g_h1h[s3 * C1 + lane]);
            float w0 = __expf(lrelu((h0 ? a0.x : a0.y) + ad_h));
            float w1 = __expf(lrelu((h0 ? a1.x : a1.y) + ad_h));
            float w2 = __expf(lrelu((h0 ? a2.x : a2.y) + ad_h));
            float w3 = __expf(lrelu((h0 ? a3.x : a3.y) + ad_h));
            acc = fmaf(w0, f0, acc); den += w0;
            acc = fmaf(w1, f1, acc); den += w1;
            acc = fmaf(w2, f2, acc); den += w2;
            acc = fmaf(w3, f3, acc); den += w3;
        }
        for (; k < m; ++k) {
            int s = __shfl_sync(0xffffffffu, sb, k);
            float2 a = __ldg(&((const float2*)g_as1)[s]);
            float f = __half2float(g_h1h[s * C1 + lane]);
            float ww = __expf(lrelu((h0 ? a.x : a.y) + ad_h));
            acc = fmaf(ww, f, acc); den += ww;
        }
    }

    float o = acc / den + b1[lane];
    o = o > 0.f ? o : (__expf(o) - 1.f);
    float c = o * W2[lane];
    #pragma unroll
    for (int off = 16; off; off >>= 1)
        c += __shfl_xor_sync(0xffffffffu, c, off);
    if (lane == 0) {
        g_sh2[d] = make_float2(c * As2[0], c);
        g_ad2[d] = c * Ad2[0];
    }
}

// ---- layer-2: warp per node, lanes stride edges -------------------------------
__global__ __launch_bounds__(256)
void k_agg2(float* __restrict__ out, const float* __restrict__ b2, int N) {
    int warp = (blockIdx.x * blockDim.x + threadIdx.x) >> 5;
    int lane = threadIdx.x & 31;
    if (warp >= N) return;
    int d = warp;
    float ad = g_ad2[d];
    float num = 0.f, den = 0.f;
    int start = g_row[d], end = g_row[d + 1];
    for (int k = start + lane; k < end; k += 32) {
        int s = g_srt[k];
        float2 p = __ldg(&((const float2*)g_sh2)[s]);
        float w = __expf(lrelu(p.x + ad));
        num = fmaf(w, p.y, num); den += w;
    }
    if (lane == 0) {
        float2 p = g_sh2[d];
        float w = __expf(lrelu(p.x + ad));
        num = fmaf(w, p.y, num); den += w;
    }
    #pragma unroll
    for (int off = 16; off; off >>= 1) {
        num += __shfl_xor_sync(0xffffffffu, num, off);
        den += __shfl_xor_sync(0xffffffffu, den, off);
    }
    if (lane == 0) out[d] = num / den + b2[0];
}

// ---- launch --------------------------------------------------------------------
extern "C" void kernel_launch(void* const* d_in, const int* in_sizes, int n_in,
                              void* d_out, int out_size) {
    const float* x     = (const float*)d_in[0];
    const int*   ei    = (const int*)  d_in[1];
    const float* W1    = (const float*)d_in[2];
    const float* a_s1  = (const float*)d_in[3];
    const float* a_d1  = (const float*)d_in[4];
    const float* b1    = (const float*)d_in[5];
    const float* W2    = (const float*)d_in[6];
    const float* a_s2  = (const float*)d_in[7];
    const float* a_d2  = (const float*)d_in[8];
    const float* b2    = (const float*)d_in[9];
    float*       out   = (float*)d_out;

    int N  = in_sizes[0] / 128;
    int E  = in_sizes[1] / 2;
    if (N > MAXN || E > MAXE) return;

    const int T = 256;
    auto blks = [T](long long n) { return (int)((n + T - 1) / T); };
    int nb = blks(N);

    // fork a second capture stream: CSR build runs concurrently with GEMM.
    // (created per call and intentionally not destroyed mid-capture; kernel_launch
    //  runs only a handful of times — graph replays never re-enter this function)
    cudaStream_t s2;
    cudaStreamCreateWithFlags(&s2, cudaStreamNonBlocking);
    cudaEvent_t evFork, evJoin;
    cudaEventCreateWithFlags(&evFork, cudaEventDisableTiming);
    cudaEventCreateWithFlags(&evJoin, cudaEventDisableTiming);

    cudaEventRecord(evFork, 0);
    cudaStreamWaitEvent(s2, evFork, 0);

    // CSR chain on forked stream
    k_zero   <<<nb, T, 0, s2>>>(N);
    k_hist   <<<blks(E), T, 0, s2>>>(ei, E);
    k_scanA  <<<nb, T, 0, s2>>>(N);
    k_scanB  <<<1, 512, 0, s2>>>(nb);
    k_scanC  <<<blks(N + 1), T, 0, s2>>>(N, E);
    k_scatter<<<blks(E), T, 0, s2>>>(ei, E);
    cudaEventRecord(evJoin, s2);

    // GEMM on main (capture) stream, concurrent with CSR build
    k_gemm<<<(N + 63) / 64, T>>>(x, W1, a_s1, a_d1, N);

    // join, then aggregation passes
    cudaStreamWaitEvent(0, evJoin, 0);
    k_agg1<<<blks((long long)N * 32), T>>>(b1, W2, a_s2, a_d2, N);
    k_agg2<<<blks((long long)N * 32), T>>>(out, b2, N);
}

// round 16
// speedup vs baseline: 2.0509x; 1.0557x over previous
#include <cuda_runtime.h>
#include <cuda_fp16.h>
#include <math.h>

// ---------------------------------------------------------------------------
// PortfolioGAT: 2-layer GAT, N=100000, 1.6M edges + self loops.
// Round 15: order-free CSR offsets (1 kernel, atomic block bases) replaces the
// 3-kernel scan; zero/cleanup folded into k_agg2 (self-restoring state);
// agg1 computes edge exps once per edge (lane-parallel) and stages
// {src,w0,w1} in smem — MUFU pressure /16. 6 kernels total, CSR || GEMM.
// ---------------------------------------------------------------------------

#define MAXN 100000
#define MAXE 1600000
#define C1 32
#define NEG_SLOPE 0.2f

// ---- scratch (zero-initialized at module load; every call restores zeros) ----
__device__ int    g_deg[MAXN];        // histogram (len per dst); zeroed by k_agg2
__device__ int    g_row[MAXN];        // region start per dst
__device__ int    g_cur[MAXN];        // scatter cursor
__device__ int    g_pos;              // global region cursor; zeroed by k_agg2
__device__ int    g_srt[MAXE];        // src ids grouped by dst
__device__ __half g_h1h[MAXN * C1];   // x @ W1, fp16
__device__ float  g_as1[MAXN * 2];
__device__ float  g_ad1[MAXN * 2];
__device__ float2 g_sh2[MAXN];        // {as2, h2}
__device__ float  g_ad2[MAXN];

__device__ __forceinline__ float lrelu(float v) { return v > 0.f ? v : NEG_SLOPE * v; }

// ---- CSR build ---------------------------------------------------------------
__global__ void k_hist(const int* __restrict__ ei, int E) {
    int i = (blockIdx.x * blockDim.x + threadIdx.x) * 2;
    if (i + 1 < E) {
        int2 d = *(const int2*)&ei[E + i];
        atomicAdd(&g_deg[d.x], 1);
        atomicAdd(&g_deg[d.y], 1);
    } else if (i < E) {
        atomicAdd(&g_deg[ei[E + i]], 1);
    }
}

// one kernel: block-local exclusive scan of degrees + one atomicAdd per block
// for the block's base. Regions are disjoint+contiguous; order irrelevant.
__global__ __launch_bounds__(256)
void k_offsets(int N) {
    __shared__ int sWarp[32];
    __shared__ int sBase;
    int i = blockIdx.x * blockDim.x + threadIdx.x;
    int lane = threadIdx.x & 31, wid = threadIdx.x >> 5;
    int v = (i < N) ? g_deg[i] : 0;

    int x = v;
    #pragma unroll
    for (int off = 1; off < 32; off <<= 1) {
        int y = __shfl_up_sync(0xffffffffu, x, off);
        if (lane >= off) x += y;
    }
    if (lane == 31) sWarp[wid] = x;
    __syncthreads();
    if (wid == 0) {
        int t = (lane < 8) ? sWarp[lane] : 0;
        #pragma unroll
        for (int off = 1; off < 8; off <<= 1) {
            int y = __shfl_up_sync(0xffffffffu, t, off);
            if (lane >= off) t += y;
        }
        sWarp[lane] = t;
        if (lane == 7) sBase = atomicAdd(&g_pos, t);   // block total -> base
    }
    __syncthreads();
    int incl = x + (wid > 0 ? sWarp[wid - 1] : 0);
    if (i < N) {
        int st = sBase + incl - v;
        g_row[i] = st;
        g_cur[i] = st;
    }
}

__global__ void k_scatter(const int* __restrict__ ei, int E) {
    int i = (blockIdx.x * blockDim.x + threadIdx.x) * 2;
    if (i + 1 < E) {
        int2 s = *(const int2*)&ei[i];
        int2 d = *(const int2*)&ei[E + i];
        g_srt[atomicAdd(&g_cur[d.x], 1)] = s.x;
        g_srt[atomicAdd(&g_cur[d.y], 1)] = s.y;
    } else if (i < E) {
        g_srt[atomicAdd(&g_cur[ei[E + i]], 1)] = ei[i];
    }
}

// ---- GEMM: h1 = x @ W1 (fp16 out), plus per-node attention projections --------
__global__ __launch_bounds__(256)
void k_gemm(const float* __restrict__ x, const float* __restrict__ W1,
            const float* __restrict__ a_s, const float* __restrict__ a_d, int N) {
    __shared__ float sW[128 * 32];
    __shared__ float sx[64 * 68];

    int tid = threadIdx.x;
    for (int i = tid; i < 128 * 32; i += 256) sW[i] = W1[i];

    int base = blockIdx.x * 64;
    int col4 = (tid & 7) * 4;
    int n0   = (tid >> 3) * 2;

    float acc[2][4] = {{0.f,0.f,0.f,0.f},{0.f,0.f,0.f,0.f}};

    for (int kc = 0; kc < 128; kc += 64) {
        __syncthreads();
        #pragma unroll
        for (int it = 0; it < 4; ++it) {
            int slot = tid + it * 256;
            int row  = slot >> 4;
            int cq   = slot & 15;
            int gn   = base + row;
            float4 v = make_float4(0.f, 0.f, 0.f, 0.f);
            if (gn < N) v = *(const float4*)&x[gn * 128 + kc + cq * 4];
            *(float4*)&sx[row * 68 + cq * 4] = v;
        }
        __syncthreads();

        #pragma unroll 16
        for (int k = 0; k < 64; ++k) {
            float4 w = *(const float4*)&sW[(kc + k) * 32 + col4];
            float x0 = sx[n0 * 68 + k];
            float x1 = sx[(n0 + 1) * 68 + k];
            acc[0][0] = fmaf(x0, w.x, acc[0][0]);
            acc[0][1] = fmaf(x0, w.y, acc[0][1]);
            acc[0][2] = fmaf(x0, w.z, acc[0][2]);
            acc[0][3] = fmaf(x0, w.w, acc[0][3]);
            acc[1][0] = fmaf(x1, w.x, acc[1][0]);
            acc[1][1] = fmaf(x1, w.y, acc[1][1]);
            acc[1][2] = fmaf(x1, w.z, acc[1][2]);
            acc[1][3] = fmaf(x1, w.w, acc[1][3]);
        }
    }

    int head = col4 >> 4;
    int cc   = col4 & 15;
    float as4[4], ad4[4];
    #pragma unroll
    for (int c = 0; c < 4; ++c) {
        as4[c] = a_s[head * 16 + cc + c];
        ad4[c] = a_d[head * 16 + cc + c];
    }
    #pragma unroll
    for (int j = 0; j < 2; ++j) {
        int n = base + n0 + j;
        float va = acc[j][0]*as4[0] + acc[j][1]*as4[1] + acc[j][2]*as4[2] + acc[j][3]*as4[3];
        float vd = acc[j][0]*ad4[0] + acc[j][1]*ad4[1] + acc[j][2]*ad4[2] + acc[j][3]*ad4[3];
        va += __shfl_xor_sync(0xffffffffu, va, 1);
        va += __shfl_xor_sync(0xffffffffu, va, 2);
        vd += __shfl_xor_sync(0xffffffffu, vd, 1);
        vd += __shfl_xor_sync(0xffffffffu, vd, 2);
        if (n < N) {
            __half2 p0 = __floats2half2_rn(acc[j][0], acc[j][1]);
            __half2 p1 = __floats2half2_rn(acc[j][2], acc[j][3]);
            __half2* hp = (__half2*)&g_h1h[n * C1 + col4];
            hp[0] = p0; hp[1] = p1;
            if ((tid & 3) == 0) {
                g_as1[n * 2 + head] = va;
                g_ad1[n * 2 + head] = vd;
            }
        }
    }
}

// ---- layer-1 aggregate + normalize + ELU + layer-2 projection, fused ---------
// One warp per dst node; lane = channel. Edge weights computed ONCE per edge
// (lane-parallel), staged in smem {src, w_head0, w_head1}, broadcast-read.
__global__ __launch_bounds__(256)
void k_agg1(const float* __restrict__ b1, const float* __restrict__ W2,
            const float* __restrict__ As2, const float* __restrict__ Ad2, int N) {
    __shared__ float4 stage[8][32];
    int warp = (blockIdx.x * blockDim.x + threadIdx.x) >> 5;
    int lane = threadIdx.x & 31;
    int wib  = (threadIdx.x >> 5);
    if (warp >= N) return;
    int d = warp;
    bool h0 = lane < 16;

    float2 adp = *(const float2*)&g_ad1[2 * d];
    float2 asp = *(const float2*)&g_as1[2 * d];
    float ad_h = h0 ? adp.x : adp.y;

    // self loop
    float w = __expf(lrelu((h0 ? asp.x : asp.y) + ad_h));
    float den = w;
    float acc = w * __half2float(g_h1h[d * C1 + lane]);

    int start = g_row[d], len = g_deg[d];
    for (int base = 0; base < len; base += 32) {
        int m = len - base; if (m > 32) m = 32;
        // stage phase: lane handles edge (base+lane)
        float4 st = make_float4(0.f, 0.f, 0.f, 0.f);
        if (lane < m) {
            int sb = g_srt[start + base + lane];
            float2 a = __ldg(&((const float2*)g_as1)[sb]);
            st.x = __int_as_float(sb);
            st.y = __expf(lrelu(a.x + adp.x));
            st.z = __expf(lrelu(a.y + adp.y));
        }
        __syncwarp();
        stage[wib][lane] = st;
        __syncwarp();

        int k = 0;
        for (; k + 4 <= m; k += 4) {
            float4 e0 = stage[wib][k];
            float4 e1 = stage[wib][k + 1];
            float4 e2 = stage[wib][k + 2];
            float4 e3 = stage[wib][k + 3];
            int s0 = __float_as_int(e0.x), s1 = __float_as_int(e1.x);
            int s2 = __float_as_int(e2.x), s3 = __float_as_int(e3.x);
            float f0 = __half2float(g_h1h[s0 * C1 + lane]);
            float f1 = __half2float(g_h1h[s1 * C1 + lane]);
            float f2 = __half2float(g_h1h[s2 * C1 + lane]);
            float f3 = __half2float(g_h1h[s3 * C1 + lane]);
            float w0 = h0 ? e0.y : e0.z;
            float w1 = h0 ? e1.y : e1.z;
            float w2 = h0 ? e2.y : e2.z;
            float w3 = h0 ? e3.y : e3.z;
            acc = fmaf(w0, f0, acc); den += w0;
            acc = fmaf(w1, f1, acc); den += w1;
            acc = fmaf(w2, f2, acc); den += w2;
            acc = fmaf(w3, f3, acc); den += w3;
        }
        for (; k < m; ++k) {
            float4 e = stage[wib][k];
            int s = __float_as_int(e.x);
            float f = __half2float(g_h1h[s * C1 + lane]);
            float ww = h0 ? e.y : e.z;
            acc = fmaf(ww, f, acc); den += ww;
        }
    }

    float o = acc / den + b1[lane];
    o = o > 0.f ? o : (__expf(o) - 1.f);
    float c = o * W2[lane];
    #pragma unroll
    for (int off = 16; off; off >>= 1)
        c += __shfl_xor_sync(0xffffffffu, c, off);
    if (lane == 0) {
        g_sh2[d] = make_float2(c * As2[0], c);
        g_ad2[d] = c * Ad2[0];
    }
}

// ---- layer-2 + state cleanup (restores zero invariants for next call) --------
__global__ __launch_bounds__(256)
void k_agg2(float* __restrict__ out, const float* __restrict__ b2, int N) {
    int warp = (blockIdx.x * blockDim.x + threadIdx.x) >> 5;
    int lane = threadIdx.x & 31;
    if (warp >= N) return;
    int d = warp;
    float ad = g_ad2[d];
    float num = 0.f, den = 0.f;
    int start = g_row[d], len = g_deg[d];
    for (int k = lane; k < len; k += 32) {
        int s = g_srt[start + k];
        float2 p = __ldg(&((const float2*)g_sh2)[s]);
        float w = __expf(lrelu(p.x + ad));
        num = fmaf(w, p.y, num); den += w;
    }
    if (lane == 0) {
        float2 p = g_sh2[d];
        float w = __expf(lrelu(p.x + ad));
        num = fmaf(w, p.y, num); den += w;
    }
    #pragma unroll
    for (int off = 16; off; off >>= 1) {
        num += __shfl_xor_sync(0xffffffffu, num, off);
        den += __shfl_xor_sync(0xffffffffu, den, off);
    }
    if (lane == 0) {
        out[d] = num / den + b2[0];
        g_deg[d] = 0;                         // restore zero for next call
        if (d == 0) g_pos = 0;
    }
}

// ---- launch --------------------------------------------------------------------
extern "C" void kernel_launch(void* const* d_in, const int* in_sizes, int n_in,
                              void* d_out, int out_size) {
    const float* x     = (const float*)d_in[0];
    const int*   ei    = (const int*)  d_in[1];
    const float* W1    = (const float*)d_in[2];
    const float* a_s1  = (const float*)d_in[3];
    const float* a_d1  = (const float*)d_in[4];
    const float* b1    = (const float*)d_in[5];
    const float* W2    = (const float*)d_in[6];
    const float* a_s2  = (const float*)d_in[7];
    const float* a_d2  = (const float*)d_in[8];
    const float* b2    = (const float*)d_in[9];
    float*       out   = (float*)d_out;

    int N  = in_sizes[0] / 128;
    int E  = in_sizes[1] / 2;
    if (N > MAXN || E > MAXE) return;

    const int T = 256;
    auto blks = [T](long long n) { return (int)((n + T - 1) / T); };

    // fork: CSR build (hist -> offsets -> scatter) runs concurrently with GEMM
    cudaStream_t s2;
    cudaStreamCreateWithFlags(&s2, cudaStreamNonBlocking);
    cudaEvent_t evFork, evJoin;
    cudaEventCreateWithFlags(&evFork, cudaEventDisableTiming);
    cudaEventCreateWithFlags(&evJoin, cudaEventDisableTiming);

    cudaEventRecord(evFork, 0);
    cudaStreamWaitEvent(s2, evFork, 0);

    k_hist   <<<blks((E + 1) / 2), T, 0, s2>>>(ei, E);
    k_offsets<<<blks(N), T, 0, s2>>>(N);
    k_scatter<<<blks((E + 1) / 2), T, 0, s2>>>(ei, E);
    cudaEventRecord(evJoin, s2);

    k_gemm<<<(N + 63) / 64, T>>>(x, W1, a_s1, a_d1, N);

    cudaStreamWaitEvent(0, evJoin, 0);
    k_agg1<<<blks((long long)N * 32), T>>>(b1, W2, a_s2, a_d2, N);
    k_agg2<<<blks((long long)N * 32), T>>>(out, b2, N);
}